// round 2
// baseline (speedup 1.0000x reference)
#include <cuda_runtime.h>
#include <math.h>

// Problem constants
#define TKN 2048          // B*N tokens
#define DM 1024           // model dim
#define NE 8              // experts
#define FFD 4096          // ffn dim
#define NH 16             // heads
#define HD 64             // head dim
#define PADROWS 3072      // token rows padded to 128 per expert segment
#define MAXTILES 24       // PADROWS/128

// ---------------- scratch (device globals; no allocation allowed) ----------------
__device__ float g_qkv[TKN * 3 * DM];
__device__ float g_ctx[TKN * DM];
__device__ float g_x[TKN * DM];
__device__ float g_tmp[TKN * DM];
__device__ float g_h[TKN * FFD];
__device__ int   g_idx0[TKN];
__device__ int   g_idx1[TKN];
__device__ float g_gw0[TKN];
__device__ float g_gw1[TKN];
__device__ int   g_perm0[PADROWS];
__device__ int   g_perm1[PADROWS];
__device__ int   g_te0[MAXTILES];
__device__ int   g_te1[MAXTILES];

// ---------------- gate: logits = x @ Wg [D,E], softmax, top-1 ----------------
__global__ void gate_kernel(const float* __restrict__ x, const float* __restrict__ Wg,
                            int* __restrict__ idx, float* __restrict__ gw) {
    int t = blockIdx.x;
    int warp = threadIdx.x >> 5, lane = threadIdx.x & 31;
    const float* xr = x + (size_t)t * DM;
    float s = 0.f;
    #pragma unroll 4
    for (int d = lane; d < DM; d += 32) s += xr[d] * Wg[d * NE + warp];
    #pragma unroll
    for (int o = 16; o; o >>= 1) s += __shfl_xor_sync(0xffffffffu, s, o);
    __shared__ float logits[NE];
    if (lane == 0) logits[warp] = s;
    __syncthreads();
    if (threadIdx.x == 0) {
        float best = logits[0]; int bi = 0;
        #pragma unroll
        for (int e = 1; e < NE; e++) if (logits[e] > best) { best = logits[e]; bi = e; }
        float sum = 0.f;
        #pragma unroll
        for (int e = 0; e < NE; e++) sum += expf(logits[e] - best);
        idx[t] = bi;
        gw[t] = 1.f / sum;   // exp(best-best)/sum
    }
}

// ---------------- scatter: group tokens by expert into 128-aligned segments ----------------
__global__ void scatter_kernel(const int* __restrict__ idx, int* __restrict__ perm,
                               int* __restrict__ tile_expert) {
    __shared__ int cnt[NE];
    __shared__ int cur[NE];
    int tid = threadIdx.x;
    if (tid < NE) cnt[tid] = 0;
    for (int i = tid; i < PADROWS; i += blockDim.x) perm[i] = -1;
    __syncthreads();
    for (int t = tid; t < TKN; t += blockDim.x) atomicAdd(&cnt[idx[t]], 1);
    __syncthreads();
    if (tid == 0) {
        int c = 0;
        for (int e = 0; e < NE; e++) {
            cur[e] = c;
            int tiles = (cnt[e] + 127) >> 7;
            for (int i = 0; i < tiles; i++) tile_expert[(c >> 7) + i] = e;
            c += tiles << 7;
        }
        for (int i = c >> 7; i < MAXTILES; i++) tile_expert[i] = -1;
    }
    __syncthreads();
    for (int t = tid; t < TKN; t += blockDim.x) {
        int p = atomicAdd(&cur[idx[t]], 1);
        perm[p] = t;
    }
}

// ---------------- generic MoE GEMM: Out[tok, col0..] = ep( gw*(In[tok]@W[e] + bias[e]) ) ----------------
// 128x128 tile, TK=8, 256 threads, 8x8 per thread, gather rows via perm, single expert per row tile.
__global__ void __launch_bounds__(256, 2)
moe_gemm(const float* __restrict__ In, const float* __restrict__ W,
         const float* __restrict__ bias, const float* __restrict__ gw,
         const int* __restrict__ perm, const int* __restrict__ tile_expert,
         float* __restrict__ Out, int K, int Nout, int gelu_flag) {
    int e = tile_expert[blockIdx.y];
    if (e < 0) return;
    int row0 = blockIdx.y << 7;
    int col0 = blockIdx.x << 7;
    __shared__ float As[8][128];
    __shared__ float Bs[8][128];
    int tid = threadIdx.x;
    int tx = tid & 15, ty = tid >> 4;

    int mA = tid >> 1;
    int kA = (tid & 1) << 2;
    int tokA = perm[row0 + mA];
    const float* inA = (tokA >= 0) ? (In + (size_t)tokA * K + kA) : In;
    int kB = tid >> 5;
    int nB = (tid & 31) << 2;
    const float* wB = W + ((size_t)e * K + kB) * Nout + col0 + nB;

    float acc[8][8];
    #pragma unroll
    for (int i = 0; i < 8; i++)
        #pragma unroll
        for (int j = 0; j < 8; j++) acc[i][j] = 0.f;

    for (int k0 = 0; k0 < K; k0 += 8) {
        float4 av = make_float4(0.f, 0.f, 0.f, 0.f);
        if (tokA >= 0) av = *(const float4*)(inA + k0);
        float4 bv = *(const float4*)(wB + (size_t)k0 * Nout);
        As[kA + 0][mA] = av.x; As[kA + 1][mA] = av.y;
        As[kA + 2][mA] = av.z; As[kA + 3][mA] = av.w;
        *(float4*)&Bs[kB][nB] = bv;
        __syncthreads();
        #pragma unroll
        for (int kk = 0; kk < 8; kk++) {
            float4 a0 = *(float4*)&As[kk][ty * 8];
            float4 a1 = *(float4*)&As[kk][ty * 8 + 4];
            float4 b0 = *(float4*)&Bs[kk][tx * 8];
            float4 b1 = *(float4*)&Bs[kk][tx * 8 + 4];
            float a[8] = {a0.x, a0.y, a0.z, a0.w, a1.x, a1.y, a1.z, a1.w};
            float b[8] = {b0.x, b0.y, b0.z, b0.w, b1.x, b1.y, b1.z, b1.w};
            #pragma unroll
            for (int i = 0; i < 8; i++)
                #pragma unroll
                for (int j = 0; j < 8; j++) acc[i][j] += a[i] * b[j];
        }
        __syncthreads();
    }

    #pragma unroll
    for (int i = 0; i < 8; i++) {
        int tok = perm[row0 + ty * 8 + i];
        if (tok < 0) continue;
        float g = gw[tok];
        const float* brow = bias + (size_t)e * Nout + col0 + tx * 8;
        float* orow = Out + (size_t)tok * Nout + col0 + tx * 8;
        float v[8];
        #pragma unroll
        for (int j = 0; j < 8; j++) {
            float val = (acc[i][j] + brow[j]) * g;
            if (gelu_flag) {
                float c = val + 0.044715f * val * val * val;
                val = 0.5f * val * (1.f + tanhf(0.7978845608028654f * c));
            }
            v[j] = val;
        }
        *(float4*)&orow[0] = make_float4(v[0], v[1], v[2], v[3]);
        *(float4*)&orow[4] = make_float4(v[4], v[5], v[6], v[7]);
    }
}

// ---------------- flash attention: BQ=64, BK=64, DH=64, 256 threads ----------------
// smem: Qs[64][64], KPs[64][65] (K tile, then overwritten with P), Vs[64][64], red[64][16]
#define ATT_SMEM_FLOATS (64 * 64 + 64 * 65 + 64 * 64 + 64 * 16)
__global__ void __launch_bounds__(256)
attn_kernel(const float* __restrict__ qkv, const unsigned char* __restrict__ mask,
            float* __restrict__ ctx) {
    extern __shared__ float sm[];
    float* Qs  = sm;                       // [64][64]
    float* KPs = Qs + 64 * 64;             // [64][65]
    float* Vs  = KPs + 64 * 65;            // [64][64]
    float* red = Vs + 64 * 64;             // [64][16]

    int bh = blockIdx.y;
    int b = bh >> 4, h = bh & 15;
    int n0 = blockIdx.x << 6;
    int tid = threadIdx.x, tx = tid & 15, ty = tid >> 4;
    int r0 = ty << 2, c0d = tx << 2;

    // load Q tile
    {
        int r = tid >> 2, d0 = (tid & 3) << 4;
        const float* qp = qkv + (size_t)(b * 1024 + n0 + r) * 3072 + h * 64 + d0;
        #pragma unroll
        for (int i = 0; i < 16; i += 4) {
            float4 v = *(const float4*)(qp + i);
            Qs[r * 64 + d0 + i + 0] = v.x; Qs[r * 64 + d0 + i + 1] = v.y;
            Qs[r * 64 + d0 + i + 2] = v.z; Qs[r * 64 + d0 + i + 3] = v.w;
        }
    }
    __syncthreads();

    float o[4][4];
    float m[4], l[4];
    #pragma unroll
    for (int i = 0; i < 4; i++) {
        m[i] = -1e30f; l[i] = 0.f;
        #pragma unroll
        for (int j = 0; j < 4; j++) o[i][j] = 0.f;
    }

    for (int kt = 0; kt < 16; kt++) {
        // load K,V tile
        {
            int c = tid >> 2, d0 = (tid & 3) << 4;
            const float* base = qkv + (size_t)(b * 1024 + kt * 64 + c) * 3072 + h * 64 + d0;
            #pragma unroll
            for (int i = 0; i < 16; i += 4) {
                float4 kv = *(const float4*)(base + 1024 + i);
                float4 vv = *(const float4*)(base + 2048 + i);
                KPs[c * 65 + d0 + i + 0] = kv.x; KPs[c * 65 + d0 + i + 1] = kv.y;
                KPs[c * 65 + d0 + i + 2] = kv.z; KPs[c * 65 + d0 + i + 3] = kv.w;
                Vs[c * 64 + d0 + i + 0] = vv.x; Vs[c * 64 + d0 + i + 1] = vv.y;
                Vs[c * 64 + d0 + i + 2] = vv.z; Vs[c * 64 + d0 + i + 3] = vv.w;
            }
        }
        __syncthreads();

        // scores S = Q K^T
        float s[4][4];
        #pragma unroll
        for (int i = 0; i < 4; i++)
            #pragma unroll
            for (int j = 0; j < 4; j++) s[i][j] = 0.f;
        for (int d = 0; d < 64; d++) {
            float qf[4], kf[4];
            #pragma unroll
            for (int i = 0; i < 4; i++) qf[i] = Qs[(r0 + i) * 64 + d];
            #pragma unroll
            for (int j = 0; j < 4; j++) kf[j] = KPs[(c0d + j) * 65 + d];
            #pragma unroll
            for (int i = 0; i < 4; i++)
                #pragma unroll
                for (int j = 0; j < 4; j++) s[i][j] += qf[i] * kf[j];
        }
        // scale + mask
        float mv[4];
        #pragma unroll
        for (int j = 0; j < 4; j++)
            mv[j] = mask[b * 1024 + kt * 64 + c0d + j] ? -10000.f : 0.f;
        #pragma unroll
        for (int i = 0; i < 4; i++)
            #pragma unroll
            for (int j = 0; j < 4; j++) s[i][j] = s[i][j] * 0.125f + mv[j];

        // row max across tx
        #pragma unroll
        for (int i = 0; i < 4; i++) {
            float rm = fmaxf(fmaxf(s[i][0], s[i][1]), fmaxf(s[i][2], s[i][3]));
            red[(r0 + i) * 16 + tx] = rm;
        }
        __syncthreads();
        float mnew[4], scale[4];
        #pragma unroll
        for (int i = 0; i < 4; i++) {
            float mx = m[i];
            #pragma unroll
            for (int q = 0; q < 16; q++) mx = fmaxf(mx, red[(r0 + i) * 16 + q]);
            mnew[i] = mx;
        }
        __syncthreads();

        // p = exp(s - mnew), row sums
        float rs[4];
        #pragma unroll
        for (int i = 0; i < 4; i++) {
            scale[i] = expf(m[i] - mnew[i]);
            float ss = 0.f;
            #pragma unroll
            for (int j = 0; j < 4; j++) { s[i][j] = expf(s[i][j] - mnew[i]); ss += s[i][j]; }
            rs[i] = ss; m[i] = mnew[i];
        }
        #pragma unroll
        for (int i = 0; i < 4; i++) red[(r0 + i) * 16 + tx] = rs[i];
        // write P into KPs (safe: all K reads completed before prior barrier)
        #pragma unroll
        for (int i = 0; i < 4; i++)
            #pragma unroll
            for (int j = 0; j < 4; j++) KPs[(r0 + i) * 65 + c0d + j] = s[i][j];
        __syncthreads();

        #pragma unroll
        for (int i = 0; i < 4; i++) {
            float ss = 0.f;
            #pragma unroll
            for (int q = 0; q < 16; q++) ss += red[(r0 + i) * 16 + q];
            l[i] = l[i] * scale[i] + ss;
            #pragma unroll
            for (int j = 0; j < 4; j++) o[i][j] *= scale[i];
        }
        // O += P @ V
        for (int c = 0; c < 64; c++) {
            float pf[4], vf[4];
            #pragma unroll
            for (int i = 0; i < 4; i++) pf[i] = KPs[(r0 + i) * 65 + c];
            #pragma unroll
            for (int j = 0; j < 4; j++) vf[j] = Vs[c * 64 + c0d + j];
            #pragma unroll
            for (int i = 0; i < 4; i++)
                #pragma unroll
                for (int j = 0; j < 4; j++) o[i][j] += pf[i] * vf[j];
        }
        __syncthreads();
    }

    #pragma unroll
    for (int i = 0; i < 4; i++) {
        int t = b * 1024 + n0 + r0 + i;
        float inv = 1.f / l[i];
        float4 v = make_float4(o[i][0] * inv, o[i][1] * inv, o[i][2] * inv, o[i][3] * inv);
        *(float4*)&ctx[(size_t)t * 1024 + h * 64 + c0d] = v;
    }
}

// ---------------- residual + layernorm: out = LN(a + b) * s + bias ----------------
__global__ void __launch_bounds__(256)
ln_kernel(const float* __restrict__ a, const float* __restrict__ b,
          const float* __restrict__ s, const float* __restrict__ bias,
          float* __restrict__ out) {
    int t = blockIdx.x;
    int base = threadIdx.x << 2;
    const float* ar = a + (size_t)t * DM;
    const float* br = b + (size_t)t * DM;
    float4 av = *(const float4*)(ar + base);
    float4 bv = *(const float4*)(br + base);
    float v[4] = {av.x + bv.x, av.y + bv.y, av.z + bv.z, av.w + bv.w};
    float s1 = v[0] + v[1] + v[2] + v[3];
    float s2 = v[0] * v[0] + v[1] * v[1] + v[2] * v[2] + v[3] * v[3];
    #pragma unroll
    for (int o = 16; o; o >>= 1) {
        s1 += __shfl_xor_sync(0xffffffffu, s1, o);
        s2 += __shfl_xor_sync(0xffffffffu, s2, o);
    }
    __shared__ float w1[8], w2[8];
    __shared__ float sh_mean, sh_inv;
    int warp = threadIdx.x >> 5, lane = threadIdx.x & 31;
    if (lane == 0) { w1[warp] = s1; w2[warp] = s2; }
    __syncthreads();
    if (threadIdx.x == 0) {
        float A = 0.f, B = 0.f;
        #pragma unroll
        for (int i = 0; i < 8; i++) { A += w1[i]; B += w2[i]; }
        float mean = A * (1.f / DM);
        float var = B * (1.f / DM) - mean * mean;
        sh_mean = mean;
        sh_inv = rsqrtf(var + 1e-5f);
    }
    __syncthreads();
    float mean = sh_mean, inv = sh_inv;
    float4 sv = *(const float4*)(s + base);
    float4 biv = *(const float4*)(bias + base);
    float4 ov;
    ov.x = (v[0] - mean) * inv * sv.x + biv.x;
    ov.y = (v[1] - mean) * inv * sv.y + biv.y;
    ov.z = (v[2] - mean) * inv * sv.z + biv.z;
    ov.w = (v[3] - mean) * inv * sv.w + biv.w;
    *(float4*)(out + (size_t)t * DM + base) = ov;
}

// ---------------- launch ----------------
extern "C" void kernel_launch(void* const* d_in, const int* in_sizes, int n_in,
                              void* d_out, int out_size) {
    const float* src     = (const float*)d_in[0];
    const unsigned char* mask = (const unsigned char*)d_in[1];
    const float* Wg_attn = (const float*)d_in[2];
    const float* Wqkv    = (const float*)d_in[3];
    const float* bqkv    = (const float*)d_in[4];
    const float* Wo      = (const float*)d_in[5];
    const float* bo      = (const float*)d_in[6];
    const float* Wg_ffn  = (const float*)d_in[7];
    const float* W1      = (const float*)d_in[8];
    const float* b1      = (const float*)d_in[9];
    const float* W2      = (const float*)d_in[10];
    const float* b2      = (const float*)d_in[11];
    const float* ln1_s   = (const float*)d_in[12];
    const float* ln1_b   = (const float*)d_in[13];
    const float* ln2_s   = (const float*)d_in[14];
    const float* ln2_b   = (const float*)d_in[15];
    float* out = (float*)d_out;

    float *qkv, *ctx, *x, *tmp, *hbuf, *gw0, *gw1;
    int *idx0, *idx1, *perm0, *perm1, *te0, *te1;
    cudaGetSymbolAddress((void**)&qkv,  g_qkv);
    cudaGetSymbolAddress((void**)&ctx,  g_ctx);
    cudaGetSymbolAddress((void**)&x,    g_x);
    cudaGetSymbolAddress((void**)&tmp,  g_tmp);
    cudaGetSymbolAddress((void**)&hbuf, g_h);
    cudaGetSymbolAddress((void**)&gw0,  g_gw0);
    cudaGetSymbolAddress((void**)&gw1,  g_gw1);
    cudaGetSymbolAddress((void**)&idx0, g_idx0);
    cudaGetSymbolAddress((void**)&idx1, g_idx1);
    cudaGetSymbolAddress((void**)&perm0, g_perm0);
    cudaGetSymbolAddress((void**)&perm1, g_perm1);
    cudaGetSymbolAddress((void**)&te0,  g_te0);
    cudaGetSymbolAddress((void**)&te1,  g_te1);

    static int att_smem_set = 0;
    int att_smem = ATT_SMEM_FLOATS * (int)sizeof(float);
    cudaFuncSetAttribute(attn_kernel, cudaFuncAttributeMaxDynamicSharedMemorySize, att_smem);
    (void)att_smem_set;

    // 1. attention gate
    gate_kernel<<<TKN, 256>>>(src, Wg_attn, idx0, gw0);
    // 2. group by expert
    scatter_kernel<<<1, 256>>>(idx0, perm0, te0);
    // 3. QKV projection (gated)
    moe_gemm<<<dim3(3 * DM / 128, MAXTILES), 256>>>(src, Wqkv, bqkv, gw0, perm0, te0,
                                                    qkv, DM, 3 * DM, 0);
    // 4. attention
    attn_kernel<<<dim3(1024 / 64, 2 * NH), 256, att_smem>>>(qkv, mask, ctx);
    // 5. output projection (gated, same gate)
    moe_gemm<<<dim3(DM / 128, MAXTILES), 256>>>(ctx, Wo, bo, gw0, perm0, te0,
                                                tmp, DM, DM, 0);
    // 6. x = LN1(src + attn_out)
    ln_kernel<<<TKN, 256>>>(src, tmp, ln1_s, ln1_b, x);
    // 7. ffn gate
    gate_kernel<<<TKN, 256>>>(x, Wg_ffn, idx1, gw1);
    scatter_kernel<<<1, 256>>>(idx1, perm1, te1);
    // 8. h = gelu(gated W1)
    moe_gemm<<<dim3(FFD / 128, MAXTILES), 256>>>(x, W1, b1, gw1, perm1, te1,
                                                 hbuf, DM, FFD, 1);
    // 9. ffn = gated W2
    moe_gemm<<<dim3(DM / 128, MAXTILES), 256>>>(hbuf, W2, b2, gw1, perm1, te1,
                                                tmp, FFD, DM, 0);
    // 10. out = LN2(x + ffn)
    ln_kernel<<<TKN, 256>>>(x, tmp, ln2_s, ln2_b, out);
}

// round 3
// speedup vs baseline: 1.0018x; 1.0018x over previous
#include <cuda_runtime.h>
#include <math.h>

// Problem constants
#define TKN 2048          // B*N tokens
#define DM 1024           // model dim
#define NE 8              // experts
#define FFD 4096          // ffn dim
#define NH 16             // heads
#define HD 64             // head dim
#define PADROWS 3072      // token rows padded to 128 per expert segment
#define MAXTILES 24       // PADROWS/128

// ---------------- scratch (device globals; no allocation allowed) ----------------
__device__ float g_qkv[TKN * 3 * DM];
__device__ float g_ctx[TKN * DM];
__device__ float g_x[TKN * DM];
__device__ float g_tmp[TKN * DM];
__device__ float g_h[TKN * FFD];
__device__ int   g_idx0[TKN];
__device__ int   g_idx1[TKN];
__device__ float g_gw0[TKN];
__device__ float g_gw1[TKN];
__device__ int   g_perm0[PADROWS];
__device__ int   g_perm1[PADROWS];
__device__ int   g_te0[MAXTILES];
__device__ int   g_te1[MAXTILES];

// ---------------- gate: logits = x @ Wg [D,E], softmax, top-1 ----------------
__global__ void gate_kernel(const float* __restrict__ x, const float* __restrict__ Wg,
                            int* __restrict__ idx, float* __restrict__ gw) {
    int t = blockIdx.x;
    int warp = threadIdx.x >> 5, lane = threadIdx.x & 31;
    const float* xr = x + (size_t)t * DM;
    float s = 0.f;
    #pragma unroll 4
    for (int d = lane; d < DM; d += 32) s += xr[d] * Wg[d * NE + warp];
    #pragma unroll
    for (int o = 16; o; o >>= 1) s += __shfl_xor_sync(0xffffffffu, s, o);
    __shared__ float logits[NE];
    if (lane == 0) logits[warp] = s;
    __syncthreads();
    if (threadIdx.x == 0) {
        float best = logits[0]; int bi = 0;
        #pragma unroll
        for (int e = 1; e < NE; e++) if (logits[e] > best) { best = logits[e]; bi = e; }
        float sum = 0.f;
        #pragma unroll
        for (int e = 0; e < NE; e++) sum += expf(logits[e] - best);
        idx[t] = bi;
        gw[t] = 1.f / sum;   // exp(best-best)/sum
    }
}

// ---------------- scatter: group tokens by expert into 128-aligned segments ----------------
__global__ void scatter_kernel(const int* __restrict__ idx, int* __restrict__ perm,
                               int* __restrict__ tile_expert) {
    __shared__ int cnt[NE];
    __shared__ int cur[NE];
    int tid = threadIdx.x;
    if (tid < NE) cnt[tid] = 0;
    for (int i = tid; i < PADROWS; i += blockDim.x) perm[i] = -1;
    __syncthreads();
    for (int t = tid; t < TKN; t += blockDim.x) atomicAdd(&cnt[idx[t]], 1);
    __syncthreads();
    if (tid == 0) {
        int c = 0;
        for (int e = 0; e < NE; e++) {
            cur[e] = c;
            int tiles = (cnt[e] + 127) >> 7;
            for (int i = 0; i < tiles; i++) tile_expert[(c >> 7) + i] = e;
            c += tiles << 7;
        }
        for (int i = c >> 7; i < MAXTILES; i++) tile_expert[i] = -1;
    }
    __syncthreads();
    for (int t = tid; t < TKN; t += blockDim.x) {
        int p = atomicAdd(&cur[idx[t]], 1);
        perm[p] = t;
    }
}

// ---------------- generic MoE GEMM: Out[tok, col0..] = ep( gw*(In[tok]@W[e] + bias[e]) ) ----------------
// 128x128 tile, TK=8, 256 threads, 8x8 per thread, gather rows via perm, single expert per row tile.
__global__ void __launch_bounds__(256, 2)
moe_gemm(const float* __restrict__ In, const float* __restrict__ W,
         const float* __restrict__ bias, const float* __restrict__ gw,
         const int* __restrict__ perm, const int* __restrict__ tile_expert,
         float* __restrict__ Out, int K, int Nout, int gelu_flag) {
    int e = tile_expert[blockIdx.y];
    if (e < 0) return;
    int row0 = blockIdx.y << 7;
    int col0 = blockIdx.x << 7;
    __shared__ float As[8][128];
    __shared__ float Bs[8][128];
    int tid = threadIdx.x;
    int tx = tid & 15, ty = tid >> 4;

    int mA = tid >> 1;
    int kA = (tid & 1) << 2;
    int tokA = perm[row0 + mA];
    const float* inA = (tokA >= 0) ? (In + (size_t)tokA * K + kA) : In;
    int kB = tid >> 5;
    int nB = (tid & 31) << 2;
    const float* wB = W + ((size_t)e * K + kB) * Nout + col0 + nB;

    float acc[8][8];
    #pragma unroll
    for (int i = 0; i < 8; i++)
        #pragma unroll
        for (int j = 0; j < 8; j++) acc[i][j] = 0.f;

    for (int k0 = 0; k0 < K; k0 += 8) {
        float4 av = make_float4(0.f, 0.f, 0.f, 0.f);
        if (tokA >= 0) av = *(const float4*)(inA + k0);
        float4 bv = *(const float4*)(wB + (size_t)k0 * Nout);
        As[kA + 0][mA] = av.x; As[kA + 1][mA] = av.y;
        As[kA + 2][mA] = av.z; As[kA + 3][mA] = av.w;
        *(float4*)&Bs[kB][nB] = bv;
        __syncthreads();
        #pragma unroll
        for (int kk = 0; kk < 8; kk++) {
            float4 a0 = *(float4*)&As[kk][ty * 8];
            float4 a1 = *(float4*)&As[kk][ty * 8 + 4];
            float4 b0 = *(float4*)&Bs[kk][tx * 8];
            float4 b1 = *(float4*)&Bs[kk][tx * 8 + 4];
            float a[8] = {a0.x, a0.y, a0.z, a0.w, a1.x, a1.y, a1.z, a1.w};
            float b[8] = {b0.x, b0.y, b0.z, b0.w, b1.x, b1.y, b1.z, b1.w};
            #pragma unroll
            for (int i = 0; i < 8; i++)
                #pragma unroll
                for (int j = 0; j < 8; j++) acc[i][j] += a[i] * b[j];
        }
        __syncthreads();
    }

    #pragma unroll
    for (int i = 0; i < 8; i++) {
        int tok = perm[row0 + ty * 8 + i];
        if (tok < 0) continue;
        float g = gw[tok];
        const float* brow = bias + (size_t)e * Nout + col0 + tx * 8;
        float* orow = Out + (size_t)tok * Nout + col0 + tx * 8;
        float v[8];
        #pragma unroll
        for (int j = 0; j < 8; j++) {
            float val = (acc[i][j] + brow[j]) * g;
            if (gelu_flag) {
                float c = val + 0.044715f * val * val * val;
                val = 0.5f * val * (1.f + tanhf(0.7978845608028654f * c));
            }
            v[j] = val;
        }
        *(float4*)&orow[0] = make_float4(v[0], v[1], v[2], v[3]);
        *(float4*)&orow[4] = make_float4(v[4], v[5], v[6], v[7]);
    }
}

// ---------------- flash attention: BQ=64, BK=64, DH=64, 256 threads ----------------
// smem: Qs[64][64], KPs[64][65] (K tile, then overwritten with P), Vs[64][64], red[64][16]
#define ATT_SMEM_FLOATS (64 * 64 + 64 * 65 + 64 * 64 + 64 * 16)
__global__ void __launch_bounds__(256)
attn_kernel(const float* __restrict__ qkv, const unsigned char* __restrict__ mask,
            float* __restrict__ ctx) {
    extern __shared__ float sm[];
    float* Qs  = sm;                       // [64][64]
    float* KPs = Qs + 64 * 64;             // [64][65]
    float* Vs  = KPs + 64 * 65;            // [64][64]
    float* red = Vs + 64 * 64;             // [64][16]

    int bh = blockIdx.y;
    int b = bh >> 4, h = bh & 15;
    int n0 = blockIdx.x << 6;
    int tid = threadIdx.x, tx = tid & 15, ty = tid >> 4;
    int r0 = ty << 2, c0d = tx << 2;

    // load Q tile
    {
        int r = tid >> 2, d0 = (tid & 3) << 4;
        const float* qp = qkv + (size_t)(b * 1024 + n0 + r) * 3072 + h * 64 + d0;
        #pragma unroll
        for (int i = 0; i < 16; i += 4) {
            float4 v = *(const float4*)(qp + i);
            Qs[r * 64 + d0 + i + 0] = v.x; Qs[r * 64 + d0 + i + 1] = v.y;
            Qs[r * 64 + d0 + i + 2] = v.z; Qs[r * 64 + d0 + i + 3] = v.w;
        }
    }
    __syncthreads();

    float o[4][4];
    float m[4], l[4];
    #pragma unroll
    for (int i = 0; i < 4; i++) {
        m[i] = -1e30f; l[i] = 0.f;
        #pragma unroll
        for (int j = 0; j < 4; j++) o[i][j] = 0.f;
    }

    for (int kt = 0; kt < 16; kt++) {
        // load K,V tile
        {
            int c = tid >> 2, d0 = (tid & 3) << 4;
            const float* base = qkv + (size_t)(b * 1024 + kt * 64 + c) * 3072 + h * 64 + d0;
            #pragma unroll
            for (int i = 0; i < 16; i += 4) {
                float4 kv = *(const float4*)(base + 1024 + i);
                float4 vv = *(const float4*)(base + 2048 + i);
                KPs[c * 65 + d0 + i + 0] = kv.x; KPs[c * 65 + d0 + i + 1] = kv.y;
                KPs[c * 65 + d0 + i + 2] = kv.z; KPs[c * 65 + d0 + i + 3] = kv.w;
                Vs[c * 64 + d0 + i + 0] = vv.x; Vs[c * 64 + d0 + i + 1] = vv.y;
                Vs[c * 64 + d0 + i + 2] = vv.z; Vs[c * 64 + d0 + i + 3] = vv.w;
            }
        }
        __syncthreads();

        // scores S = Q K^T
        float s[4][4];
        #pragma unroll
        for (int i = 0; i < 4; i++)
            #pragma unroll
            for (int j = 0; j < 4; j++) s[i][j] = 0.f;
        for (int d = 0; d < 64; d++) {
            float qf[4], kf[4];
            #pragma unroll
            for (int i = 0; i < 4; i++) qf[i] = Qs[(r0 + i) * 64 + d];
            #pragma unroll
            for (int j = 0; j < 4; j++) kf[j] = KPs[(c0d + j) * 65 + d];
            #pragma unroll
            for (int i = 0; i < 4; i++)
                #pragma unroll
                for (int j = 0; j < 4; j++) s[i][j] += qf[i] * kf[j];
        }
        // scale + mask
        float mv[4];
        #pragma unroll
        for (int j = 0; j < 4; j++)
            mv[j] = mask[b * 1024 + kt * 64 + c0d + j] ? -10000.f : 0.f;
        #pragma unroll
        for (int i = 0; i < 4; i++)
            #pragma unroll
            for (int j = 0; j < 4; j++) s[i][j] = s[i][j] * 0.125f + mv[j];

        // row max across tx
        #pragma unroll
        for (int i = 0; i < 4; i++) {
            float rm = fmaxf(fmaxf(s[i][0], s[i][1]), fmaxf(s[i][2], s[i][3]));
            red[(r0 + i) * 16 + tx] = rm;
        }
        __syncthreads();
        float mnew[4], scale[4];
        #pragma unroll
        for (int i = 0; i < 4; i++) {
            float mx = m[i];
            #pragma unroll
            for (int q = 0; q < 16; q++) mx = fmaxf(mx, red[(r0 + i) * 16 + q]);
            mnew[i] = mx;
        }
        __syncthreads();

        // p = exp(s - mnew), row sums
        float rs[4];
        #pragma unroll
        for (int i = 0; i < 4; i++) {
            scale[i] = expf(m[i] - mnew[i]);
            float ss = 0.f;
            #pragma unroll
            for (int j = 0; j < 4; j++) { s[i][j] = expf(s[i][j] - mnew[i]); ss += s[i][j]; }
            rs[i] = ss; m[i] = mnew[i];
        }
        #pragma unroll
        for (int i = 0; i < 4; i++) red[(r0 + i) * 16 + tx] = rs[i];
        // write P into KPs (safe: all K reads completed before prior barrier)
        #pragma unroll
        for (int i = 0; i < 4; i++)
            #pragma unroll
            for (int j = 0; j < 4; j++) KPs[(r0 + i) * 65 + c0d + j] = s[i][j];
        __syncthreads();

        #pragma unroll
        for (int i = 0; i < 4; i++) {
            float ss = 0.f;
            #pragma unroll
            for (int q = 0; q < 16; q++) ss += red[(r0 + i) * 16 + q];
            l[i] = l[i] * scale[i] + ss;
            #pragma unroll
            for (int j = 0; j < 4; j++) o[i][j] *= scale[i];
        }
        // O += P @ V
        for (int c = 0; c < 64; c++) {
            float pf[4], vf[4];
            #pragma unroll
            for (int i = 0; i < 4; i++) pf[i] = KPs[(r0 + i) * 65 + c];
            #pragma unroll
            for (int j = 0; j < 4; j++) vf[j] = Vs[c * 64 + c0d + j];
            #pragma unroll
            for (int i = 0; i < 4; i++)
                #pragma unroll
                for (int j = 0; j < 4; j++) o[i][j] += pf[i] * vf[j];
        }
        __syncthreads();
    }

    #pragma unroll
    for (int i = 0; i < 4; i++) {
        int t = b * 1024 + n0 + r0 + i;
        float inv = 1.f / l[i];
        float4 v = make_float4(o[i][0] * inv, o[i][1] * inv, o[i][2] * inv, o[i][3] * inv);
        *(float4*)&ctx[(size_t)t * 1024 + h * 64 + c0d] = v;
    }
}

// ---------------- residual + layernorm: out = LN(a + b) * s + bias ----------------
__global__ void __launch_bounds__(256)
ln_kernel(const float* __restrict__ a, const float* __restrict__ b,
          const float* __restrict__ s, const float* __restrict__ bias,
          float* __restrict__ out) {
    int t = blockIdx.x;
    int base = threadIdx.x << 2;
    const float* ar = a + (size_t)t * DM;
    const float* br = b + (size_t)t * DM;
    float4 av = *(const float4*)(ar + base);
    float4 bv = *(const float4*)(br + base);
    float v[4] = {av.x + bv.x, av.y + bv.y, av.z + bv.z, av.w + bv.w};
    float s1 = v[0] + v[1] + v[2] + v[3];
    float s2 = v[0] * v[0] + v[1] * v[1] + v[2] * v[2] + v[3] * v[3];
    #pragma unroll
    for (int o = 16; o; o >>= 1) {
        s1 += __shfl_xor_sync(0xffffffffu, s1, o);
        s2 += __shfl_xor_sync(0xffffffffu, s2, o);
    }
    __shared__ float w1[8], w2[8];
    __shared__ float sh_mean, sh_inv;
    int warp = threadIdx.x >> 5, lane = threadIdx.x & 31;
    if (lane == 0) { w1[warp] = s1; w2[warp] = s2; }
    __syncthreads();
    if (threadIdx.x == 0) {
        float A = 0.f, B = 0.f;
        #pragma unroll
        for (int i = 0; i < 8; i++) { A += w1[i]; B += w2[i]; }
        float mean = A * (1.f / DM);
        float var = B * (1.f / DM) - mean * mean;
        sh_mean = mean;
        sh_inv = rsqrtf(var + 1e-5f);
    }
    __syncthreads();
    float mean = sh_mean, inv = sh_inv;
    float4 sv = *(const float4*)(s + base);
    float4 biv = *(const float4*)(bias + base);
    float4 ov;
    ov.x = (v[0] - mean) * inv * sv.x + biv.x;
    ov.y = (v[1] - mean) * inv * sv.y + biv.y;
    ov.z = (v[2] - mean) * inv * sv.z + biv.z;
    ov.w = (v[3] - mean) * inv * sv.w + biv.w;
    *(float4*)(out + (size_t)t * DM + base) = ov;
}

// ---------------- launch ----------------
extern "C" void kernel_launch(void* const* d_in, const int* in_sizes, int n_in,
                              void* d_out, int out_size) {
    const float* src     = (const float*)d_in[0];
    const unsigned char* mask = (const unsigned char*)d_in[1];
    const float* Wg_attn = (const float*)d_in[2];
    const float* Wqkv    = (const float*)d_in[3];
    const float* bqkv    = (const float*)d_in[4];
    const float* Wo      = (const float*)d_in[5];
    const float* bo      = (const float*)d_in[6];
    const float* Wg_ffn  = (const float*)d_in[7];
    const float* W1      = (const float*)d_in[8];
    const float* b1      = (const float*)d_in[9];
    const float* W2      = (const float*)d_in[10];
    const float* b2      = (const float*)d_in[11];
    const float* ln1_s   = (const float*)d_in[12];
    const float* ln1_b   = (const float*)d_in[13];
    const float* ln2_s   = (const float*)d_in[14];
    const float* ln2_b   = (const float*)d_in[15];
    float* out = (float*)d_out;

    float *qkv, *ctx, *x, *tmp, *hbuf, *gw0, *gw1;
    int *idx0, *idx1, *perm0, *perm1, *te0, *te1;
    cudaGetSymbolAddress((void**)&qkv,  g_qkv);
    cudaGetSymbolAddress((void**)&ctx,  g_ctx);
    cudaGetSymbolAddress((void**)&x,    g_x);
    cudaGetSymbolAddress((void**)&tmp,  g_tmp);
    cudaGetSymbolAddress((void**)&hbuf, g_h);
    cudaGetSymbolAddress((void**)&gw0,  g_gw0);
    cudaGetSymbolAddress((void**)&gw1,  g_gw1);
    cudaGetSymbolAddress((void**)&idx0, g_idx0);
    cudaGetSymbolAddress((void**)&idx1, g_idx1);
    cudaGetSymbolAddress((void**)&perm0, g_perm0);
    cudaGetSymbolAddress((void**)&perm1, g_perm1);
    cudaGetSymbolAddress((void**)&te0,  g_te0);
    cudaGetSymbolAddress((void**)&te1,  g_te1);

    static int att_smem_set = 0;
    int att_smem = ATT_SMEM_FLOATS * (int)sizeof(float);
    cudaFuncSetAttribute(attn_kernel, cudaFuncAttributeMaxDynamicSharedMemorySize, att_smem);
    (void)att_smem_set;

    // 1. attention gate
    gate_kernel<<<TKN, 256>>>(src, Wg_attn, idx0, gw0);
    // 2. group by expert
    scatter_kernel<<<1, 256>>>(idx0, perm0, te0);
    // 3. QKV projection (gated)
    moe_gemm<<<dim3(3 * DM / 128, MAXTILES), 256>>>(src, Wqkv, bqkv, gw0, perm0, te0,
                                                    qkv, DM, 3 * DM, 0);
    // 4. attention
    attn_kernel<<<dim3(1024 / 64, 2 * NH), 256, att_smem>>>(qkv, mask, ctx);
    // 5. output projection (gated, same gate)
    moe_gemm<<<dim3(DM / 128, MAXTILES), 256>>>(ctx, Wo, bo, gw0, perm0, te0,
                                                tmp, DM, DM, 0);
    // 6. x = LN1(src + attn_out)
    ln_kernel<<<TKN, 256>>>(src, tmp, ln1_s, ln1_b, x);
    // 7. ffn gate
    gate_kernel<<<TKN, 256>>>(x, Wg_ffn, idx1, gw1);
    scatter_kernel<<<1, 256>>>(idx1, perm1, te1);
    // 8. h = gelu(gated W1)
    moe_gemm<<<dim3(FFD / 128, MAXTILES), 256>>>(x, W1, b1, gw1, perm1, te1,
                                                 hbuf, DM, FFD, 1);
    // 9. ffn = gated W2
    moe_gemm<<<dim3(DM / 128, MAXTILES), 256>>>(hbuf, W2, b2, gw1, perm1, te1,
                                                tmp, FFD, DM, 0);
    // 10. out = LN2(x + ffn)
    ln_kernel<<<TKN, 256>>>(x, tmp, ln2_s, ln2_b, out);
}

// round 5
// speedup vs baseline: 1.9161x; 1.9127x over previous
#include <cuda_runtime.h>
#include <math.h>
#include <stdint.h>

// Problem constants
#define TKN 2048          // B*N tokens
#define DM 1024           // model dim
#define NE 8              // experts
#define FFD 4096          // ffn dim
#define NH 16             // heads
#define HD 64             // head dim
#define PADROWS 3072      // token rows padded to 128 per expert segment
#define MAXTILES 24       // PADROWS/128

// ---------------- scratch (device globals; no allocation allowed) ----------------
__device__ float g_qkv[TKN * 3 * DM];
__device__ float g_ctx[TKN * DM];
__device__ float g_x[TKN * DM];
__device__ float g_tmp[TKN * DM];
__device__ float g_h[TKN * FFD];
__device__ int   g_idx0[TKN];
__device__ int   g_idx1[TKN];
__device__ float g_gw0[TKN];
__device__ float g_gw1[TKN];
__device__ int   g_perm0[PADROWS];
__device__ int   g_perm1[PADROWS];
__device__ int   g_te0[MAXTILES];
__device__ int   g_te1[MAXTILES];

__device__ __forceinline__ uint32_t f2tf32(float x) {
    uint32_t r;
    asm("cvt.rna.tf32.f32 %0, %1;" : "=r"(r) : "f"(x));
    return r;
}
__device__ __forceinline__ void mma_tf32(float& c0, float& c1, float& c2, float& c3,
                                         uint32_t a0, uint32_t a1, uint32_t a2, uint32_t a3,
                                         uint32_t b0, uint32_t b1) {
    asm volatile(
        "mma.sync.aligned.m16n8k8.row.col.f32.tf32.tf32.f32 "
        "{%0,%1,%2,%3}, {%4,%5,%6,%7}, {%8,%9}, {%0,%1,%2,%3};"
        : "+f"(c0), "+f"(c1), "+f"(c2), "+f"(c3)
        : "r"(a0), "r"(a1), "r"(a2), "r"(a3), "r"(b0), "r"(b1));
}

// ---------------- gate: logits = x @ Wg [D,E], softmax, top-1 ----------------
__global__ void gate_kernel(const float* __restrict__ x, const float* __restrict__ Wg,
                            int* __restrict__ idx, float* __restrict__ gw) {
    int t = blockIdx.x;
    int warp = threadIdx.x >> 5, lane = threadIdx.x & 31;
    const float* xr = x + (size_t)t * DM;
    float s = 0.f;
    #pragma unroll 4
    for (int d = lane; d < DM; d += 32) s += xr[d] * Wg[d * NE + warp];
    #pragma unroll
    for (int o = 16; o; o >>= 1) s += __shfl_xor_sync(0xffffffffu, s, o);
    __shared__ float logits[NE];
    if (lane == 0) logits[warp] = s;
    __syncthreads();
    if (threadIdx.x == 0) {
        float best = logits[0]; int bi = 0;
        #pragma unroll
        for (int e = 1; e < NE; e++) if (logits[e] > best) { best = logits[e]; bi = e; }
        float sum = 0.f;
        #pragma unroll
        for (int e = 0; e < NE; e++) sum += expf(logits[e] - best);
        idx[t] = bi;
        gw[t] = 1.f / sum;
    }
}

// ---------------- scatter: group tokens by expert into 128-aligned segments ----------------
__global__ void scatter_kernel(const int* __restrict__ idx, int* __restrict__ perm,
                               int* __restrict__ tile_expert) {
    __shared__ int cnt[NE];
    __shared__ int cur[NE];
    int tid = threadIdx.x;
    if (tid < NE) cnt[tid] = 0;
    for (int i = tid; i < PADROWS; i += blockDim.x) perm[i] = -1;
    __syncthreads();
    for (int t = tid; t < TKN; t += blockDim.x) atomicAdd(&cnt[idx[t]], 1);
    __syncthreads();
    if (tid == 0) {
        int c = 0;
        for (int e = 0; e < NE; e++) {
            cur[e] = c;
            int tiles = (cnt[e] + 127) >> 7;
            for (int i = 0; i < tiles; i++) tile_expert[(c >> 7) + i] = e;
            c += tiles << 7;
        }
        for (int i = c >> 7; i < MAXTILES; i++) tile_expert[i] = -1;
    }
    __syncthreads();
    for (int t = tid; t < TKN; t += blockDim.x) {
        int p = atomicAdd(&cur[idx[t]], 1);
        perm[p] = t;
    }
}

// ============ tf32 mma.sync MoE GEMM: Out[tok] = ep(gw*(In[tok]@W[e] + b[e])) ============
// 128x128 CTA tile, BK=16, 8 warps (4M x 2N), warp tile 32x64, m16n8k8 tf32.
// smem k-major [16][136] for both A and B: fragment LDS conflict-free.
#define KSTRIDE 136
#define STGW (16 * KSTRIDE)   // words per stage = 2176

__global__ void __launch_bounds__(256, 2)
moe_gemm_mma(const float* __restrict__ In, const float* __restrict__ W,
             const float* __restrict__ bias, const float* __restrict__ gw,
             const int* __restrict__ perm, const int* __restrict__ tile_expert,
             float* __restrict__ Out, int K, int Nout, int gelu_flag) {
    int e = tile_expert[blockIdx.y];
    if (e < 0) return;
    __shared__ uint32_t SA[2][STGW];
    __shared__ uint32_t SB[2][STGW];

    int tid = threadIdx.x, wid = tid >> 5, lane = tid & 31;
    int g = lane >> 2, tg = lane & 3;
    int warp_m = wid & 3, warp_n = wid >> 2;
    int row0 = blockIdx.y << 7, col0 = blockIdx.x << 7;

    // ---- global load mappings ----
    // A: thread handles row mS (0..127), k-half kqS (0 or 8) of each 16-chunk
    int mS = tid & 127;
    int kqS = (tid >> 7) << 3;
    int tokA = perm[row0 + mS];
    const float* aptr = (tokA >= 0) ? (In + (size_t)tokA * K + kqS) : In;
    // B: thread handles k row kBs (0..15), 8 cols at nBs
    int kBs = tid >> 4;
    int nBs = (tid & 15) << 3;
    const float* bptr = W + ((size_t)e * K + kBs) * Nout + col0 + nBs;

    float acc[2][8][4];
    #pragma unroll
    for (int mi = 0; mi < 2; mi++)
        #pragma unroll
        for (int ni = 0; ni < 8; ni++)
            #pragma unroll
            for (int q = 0; q < 4; q++) acc[mi][ni][q] = 0.f;

    int nchunk = K >> 4;

    // ---- prologue: chunk 0 into buffer 0 ----
    {
        float4 av0 = make_float4(0.f,0.f,0.f,0.f), av1 = av0;
        if (tokA >= 0) { av0 = *(const float4*)(aptr); av1 = *(const float4*)(aptr + 4); }
        float4 bv0 = *(const float4*)(bptr);
        float4 bv1 = *(const float4*)(bptr + 4);
        SA[0][(kqS + 0) * KSTRIDE + mS] = f2tf32(av0.x);
        SA[0][(kqS + 1) * KSTRIDE + mS] = f2tf32(av0.y);
        SA[0][(kqS + 2) * KSTRIDE + mS] = f2tf32(av0.z);
        SA[0][(kqS + 3) * KSTRIDE + mS] = f2tf32(av0.w);
        SA[0][(kqS + 4) * KSTRIDE + mS] = f2tf32(av1.x);
        SA[0][(kqS + 5) * KSTRIDE + mS] = f2tf32(av1.y);
        SA[0][(kqS + 6) * KSTRIDE + mS] = f2tf32(av1.z);
        SA[0][(kqS + 7) * KSTRIDE + mS] = f2tf32(av1.w);
        uint32_t* bdst = &SB[0][kBs * KSTRIDE + nBs];
        bdst[0] = f2tf32(bv0.x); bdst[1] = f2tf32(bv0.y);
        bdst[2] = f2tf32(bv0.z); bdst[3] = f2tf32(bv0.w);
        bdst[4] = f2tf32(bv1.x); bdst[5] = f2tf32(bv1.y);
        bdst[6] = f2tf32(bv1.z); bdst[7] = f2tf32(bv1.w);
    }
    __syncthreads();

    int am0 = warp_m * 32 + g;
    int bn0 = warp_n * 64 + g;

    for (int c = 0; c < nchunk; c++) {
        int buf = c & 1;
        bool has_next = (c + 1) < nchunk;
        float4 av0, av1, bv0, bv1;
        if (has_next) {
            int k0 = (c + 1) << 4;
            if (tokA >= 0) {
                av0 = *(const float4*)(aptr + k0);
                av1 = *(const float4*)(aptr + k0 + 4);
            } else { av0 = make_float4(0.f,0.f,0.f,0.f); av1 = av0; }
            const float* bp = bptr + (size_t)k0 * Nout;
            bv0 = *(const float4*)(bp);
            bv1 = *(const float4*)(bp + 4);
        }

        // ---- compute chunk c ----
        const uint32_t* Ab = SA[buf];
        const uint32_t* Bb = SB[buf];
        #pragma unroll
        for (int ks = 0; ks < 2; ks++) {
            int kb = ks << 3;
            uint32_t a[2][4];
            #pragma unroll
            for (int mi = 0; mi < 2; mi++) {
                int m = am0 + mi * 16;
                a[mi][0] = Ab[(kb + tg) * KSTRIDE + m];
                a[mi][1] = Ab[(kb + tg) * KSTRIDE + m + 8];
                a[mi][2] = Ab[(kb + tg + 4) * KSTRIDE + m];
                a[mi][3] = Ab[(kb + tg + 4) * KSTRIDE + m + 8];
            }
            #pragma unroll
            for (int ni = 0; ni < 8; ni++) {
                int n = bn0 + ni * 8;
                uint32_t b0 = Bb[(kb + tg) * KSTRIDE + n];
                uint32_t b1 = Bb[(kb + tg + 4) * KSTRIDE + n];
                mma_tf32(acc[0][ni][0], acc[0][ni][1], acc[0][ni][2], acc[0][ni][3],
                         a[0][0], a[0][1], a[0][2], a[0][3], b0, b1);
                mma_tf32(acc[1][ni][0], acc[1][ni][1], acc[1][ni][2], acc[1][ni][3],
                         a[1][0], a[1][1], a[1][2], a[1][3], b0, b1);
            }
        }

        if (has_next) {
            int nb = buf ^ 1;
            SA[nb][(kqS + 0) * KSTRIDE + mS] = f2tf32(av0.x);
            SA[nb][(kqS + 1) * KSTRIDE + mS] = f2tf32(av0.y);
            SA[nb][(kqS + 2) * KSTRIDE + mS] = f2tf32(av0.z);
            SA[nb][(kqS + 3) * KSTRIDE + mS] = f2tf32(av0.w);
            SA[nb][(kqS + 4) * KSTRIDE + mS] = f2tf32(av1.x);
            SA[nb][(kqS + 5) * KSTRIDE + mS] = f2tf32(av1.y);
            SA[nb][(kqS + 6) * KSTRIDE + mS] = f2tf32(av1.z);
            SA[nb][(kqS + 7) * KSTRIDE + mS] = f2tf32(av1.w);
            uint32_t* bdst = &SB[nb][kBs * KSTRIDE + nBs];
            bdst[0] = f2tf32(bv0.x); bdst[1] = f2tf32(bv0.y);
            bdst[2] = f2tf32(bv0.z); bdst[3] = f2tf32(bv0.w);
            bdst[4] = f2tf32(bv1.x); bdst[5] = f2tf32(bv1.y);
            bdst[6] = f2tf32(bv1.z); bdst[7] = f2tf32(bv1.w);
            __syncthreads();
        }
    }

    // ---- epilogue: rows mbase + {0,8,16,24}, cols warp_n*64 + ni*8 + 2*tg ----
    int tok[4]; float gwv[4];
    #pragma unroll
    for (int q = 0; q < 4; q++) {
        int r = row0 + warp_m * 32 + g + q * 8;
        tok[q] = perm[r];
        gwv[q] = (tok[q] >= 0) ? gw[tok[q]] : 0.f;
    }
    #pragma unroll
    for (int ni = 0; ni < 8; ni++) {
        int col = col0 + warp_n * 64 + ni * 8 + 2 * tg;
        float2 bs2 = *(const float2*)&bias[(size_t)e * Nout + col];
        #pragma unroll
        for (int mi = 0; mi < 2; mi++) {
            #pragma unroll
            for (int half = 0; half < 2; half++) {
                int q = mi * 2 + half;
                if (tok[q] < 0) continue;
                float v0 = (acc[mi][ni][half * 2 + 0] + bs2.x) * gwv[q];
                float v1 = (acc[mi][ni][half * 2 + 1] + bs2.y) * gwv[q];
                if (gelu_flag) {
                    float c0 = v0 + 0.044715f * v0 * v0 * v0;
                    v0 = 0.5f * v0 * (1.f + tanhf(0.7978845608028654f * c0));
                    float c1 = v1 + 0.044715f * v1 * v1 * v1;
                    v1 = 0.5f * v1 * (1.f + tanhf(0.7978845608028654f * c1));
                }
                *(float2*)&Out[(size_t)tok[q] * Nout + col] = make_float2(v0, v1);
            }
        }
    }
}

// ---------------- flash attention: BQ=64, BK=64, DH=64, 256 threads ----------------
#define ATT_SMEM_FLOATS (64 * 64 + 64 * 65 + 64 * 64 + 64 * 16)
__global__ void __launch_bounds__(256)
attn_kernel(const float* __restrict__ qkv, const unsigned char* __restrict__ mask,
            float* __restrict__ ctx) {
    extern __shared__ float sm[];
    float* Qs  = sm;
    float* KPs = Qs + 64 * 64;
    float* Vs  = KPs + 64 * 65;
    float* red = Vs + 64 * 64;

    int bh = blockIdx.y;
    int b = bh >> 4, h = bh & 15;
    int n0 = blockIdx.x << 6;
    int tid = threadIdx.x, tx = tid & 15, ty = tid >> 4;
    int r0 = ty << 2, c0d = tx << 2;

    {
        int r = tid >> 2, d0 = (tid & 3) << 4;
        const float* qp = qkv + (size_t)(b * 1024 + n0 + r) * 3072 + h * 64 + d0;
        #pragma unroll
        for (int i = 0; i < 16; i += 4) {
            float4 v = *(const float4*)(qp + i);
            Qs[r * 64 + d0 + i + 0] = v.x; Qs[r * 64 + d0 + i + 1] = v.y;
            Qs[r * 64 + d0 + i + 2] = v.z; Qs[r * 64 + d0 + i + 3] = v.w;
        }
    }
    __syncthreads();

    float o[4][4];
    float m[4], l[4];
    #pragma unroll
    for (int i = 0; i < 4; i++) {
        m[i] = -1e30f; l[i] = 0.f;
        #pragma unroll
        for (int j = 0; j < 4; j++) o[i][j] = 0.f;
    }

    for (int kt = 0; kt < 16; kt++) {
        {
            int c = tid >> 2, d0 = (tid & 3) << 4;
            const float* base = qkv + (size_t)(b * 1024 + kt * 64 + c) * 3072 + h * 64 + d0;
            #pragma unroll
            for (int i = 0; i < 16; i += 4) {
                float4 kv = *(const float4*)(base + 1024 + i);
                float4 vv = *(const float4*)(base + 2048 + i);
                KPs[c * 65 + d0 + i + 0] = kv.x; KPs[c * 65 + d0 + i + 1] = kv.y;
                KPs[c * 65 + d0 + i + 2] = kv.z; KPs[c * 65 + d0 + i + 3] = kv.w;
                Vs[c * 64 + d0 + i + 0] = vv.x; Vs[c * 64 + d0 + i + 1] = vv.y;
                Vs[c * 64 + d0 + i + 2] = vv.z; Vs[c * 64 + d0 + i + 3] = vv.w;
            }
        }
        __syncthreads();

        float s[4][4];
        #pragma unroll
        for (int i = 0; i < 4; i++)
            #pragma unroll
            for (int j = 0; j < 4; j++) s[i][j] = 0.f;
        for (int d = 0; d < 64; d++) {
            float qf[4], kf[4];
            #pragma unroll
            for (int i = 0; i < 4; i++) qf[i] = Qs[(r0 + i) * 64 + d];
            #pragma unroll
            for (int j = 0; j < 4; j++) kf[j] = KPs[(c0d + j) * 65 + d];
            #pragma unroll
            for (int i = 0; i < 4; i++)
                #pragma unroll
                for (int j = 0; j < 4; j++) s[i][j] += qf[i] * kf[j];
        }
        float mv[4];
        #pragma unroll
        for (int j = 0; j < 4; j++)
            mv[j] = mask[b * 1024 + kt * 64 + c0d + j] ? -10000.f : 0.f;
        #pragma unroll
        for (int i = 0; i < 4; i++)
            #pragma unroll
            for (int j = 0; j < 4; j++) s[i][j] = s[i][j] * 0.125f + mv[j];

        #pragma unroll
        for (int i = 0; i < 4; i++) {
            float rm = fmaxf(fmaxf(s[i][0], s[i][1]), fmaxf(s[i][2], s[i][3]));
            red[(r0 + i) * 16 + tx] = rm;
        }
        __syncthreads();
        float mnew[4], scale[4];
        #pragma unroll
        for (int i = 0; i < 4; i++) {
            float mx = m[i];
            #pragma unroll
            for (int q = 0; q < 16; q++) mx = fmaxf(mx, red[(r0 + i) * 16 + q]);
            mnew[i] = mx;
        }
        __syncthreads();

        float rs[4];
        #pragma unroll
        for (int i = 0; i < 4; i++) {
            scale[i] = expf(m[i] - mnew[i]);
            float ss = 0.f;
            #pragma unroll
            for (int j = 0; j < 4; j++) { s[i][j] = expf(s[i][j] - mnew[i]); ss += s[i][j]; }
            rs[i] = ss; m[i] = mnew[i];
        }
        #pragma unroll
        for (int i = 0; i < 4; i++) red[(r0 + i) * 16 + tx] = rs[i];
        #pragma unroll
        for (int i = 0; i < 4; i++)
            #pragma unroll
            for (int j = 0; j < 4; j++) KPs[(r0 + i) * 65 + c0d + j] = s[i][j];
        __syncthreads();

        #pragma unroll
        for (int i = 0; i < 4; i++) {
            float ss = 0.f;
            #pragma unroll
            for (int q = 0; q < 16; q++) ss += red[(r0 + i) * 16 + q];
            l[i] = l[i] * scale[i] + ss;
            #pragma unroll
            for (int j = 0; j < 4; j++) o[i][j] *= scale[i];
        }
        for (int c = 0; c < 64; c++) {
            float pf[4], vf[4];
            #pragma unroll
            for (int i = 0; i < 4; i++) pf[i] = KPs[(r0 + i) * 65 + c];
            #pragma unroll
            for (int j = 0; j < 4; j++) vf[j] = Vs[c * 64 + c0d + j];
            #pragma unroll
            for (int i = 0; i < 4; i++)
                #pragma unroll
                for (int j = 0; j < 4; j++) o[i][j] += pf[i] * vf[j];
        }
        __syncthreads();
    }

    #pragma unroll
    for (int i = 0; i < 4; i++) {
        int t = b * 1024 + n0 + r0 + i;
        float inv = 1.f / l[i];
        float4 v = make_float4(o[i][0] * inv, o[i][1] * inv, o[i][2] * inv, o[i][3] * inv);
        *(float4*)&ctx[(size_t)t * 1024 + h * 64 + c0d] = v;
    }
}

// ---------------- residual + layernorm ----------------
__global__ void __launch_bounds__(256)
ln_kernel(const float* __restrict__ a, const float* __restrict__ b,
          const float* __restrict__ s, const float* __restrict__ bias,
          float* __restrict__ out) {
    int t = blockIdx.x;
    int base = threadIdx.x << 2;
    const float* ar = a + (size_t)t * DM;
    const float* br = b + (size_t)t * DM;
    float4 av = *(const float4*)(ar + base);
    float4 bv = *(const float4*)(br + base);
    float v[4] = {av.x + bv.x, av.y + bv.y, av.z + bv.z, av.w + bv.w};
    float s1 = v[0] + v[1] + v[2] + v[3];
    float s2 = v[0] * v[0] + v[1] * v[1] + v[2] * v[2] + v[3] * v[3];
    #pragma unroll
    for (int o = 16; o; o >>= 1) {
        s1 += __shfl_xor_sync(0xffffffffu, s1, o);
        s2 += __shfl_xor_sync(0xffffffffu, s2, o);
    }
    __shared__ float w1[8], w2[8];
    __shared__ float sh_mean, sh_inv;
    int warp = threadIdx.x >> 5, lane = threadIdx.x & 31;
    if (lane == 0) { w1[warp] = s1; w2[warp] = s2; }
    __syncthreads();
    if (threadIdx.x == 0) {
        float A = 0.f, B = 0.f;
        #pragma unroll
        for (int i = 0; i < 8; i++) { A += w1[i]; B += w2[i]; }
        float mean = A * (1.f / DM);
        float var = B * (1.f / DM) - mean * mean;
        sh_mean = mean;
        sh_inv = rsqrtf(var + 1e-5f);
    }
    __syncthreads();
    float mean = sh_mean, inv = sh_inv;
    float4 sv = *(const float4*)(s + base);
    float4 biv = *(const float4*)(bias + base);
    float4 ov;
    ov.x = (v[0] - mean) * inv * sv.x + biv.x;
    ov.y = (v[1] - mean) * inv * sv.y + biv.y;
    ov.z = (v[2] - mean) * inv * sv.z + biv.z;
    ov.w = (v[3] - mean) * inv * sv.w + biv.w;
    *(float4*)(out + (size_t)t * DM + base) = ov;
}

// ---------------- launch ----------------
extern "C" void kernel_launch(void* const* d_in, const int* in_sizes, int n_in,
                              void* d_out, int out_size) {
    const float* src     = (const float*)d_in[0];
    const unsigned char* mask = (const unsigned char*)d_in[1];
    const float* Wg_attn = (const float*)d_in[2];
    const float* Wqkv    = (const float*)d_in[3];
    const float* bqkv    = (const float*)d_in[4];
    const float* Wo      = (const float*)d_in[5];
    const float* bo      = (const float*)d_in[6];
    const float* Wg_ffn  = (const float*)d_in[7];
    const float* W1      = (const float*)d_in[8];
    const float* b1      = (const float*)d_in[9];
    const float* W2      = (const float*)d_in[10];
    const float* b2      = (const float*)d_in[11];
    const float* ln1_s   = (const float*)d_in[12];
    const float* ln1_b   = (const float*)d_in[13];
    const float* ln2_s   = (const float*)d_in[14];
    const float* ln2_b   = (const float*)d_in[15];
    float* out = (float*)d_out;

    float *qkv, *ctx, *x, *tmp, *hbuf, *gw0, *gw1;
    int *idx0, *idx1, *perm0, *perm1, *te0, *te1;
    cudaGetSymbolAddress((void**)&qkv,  g_qkv);
    cudaGetSymbolAddress((void**)&ctx,  g_ctx);
    cudaGetSymbolAddress((void**)&x,    g_x);
    cudaGetSymbolAddress((void**)&tmp,  g_tmp);
    cudaGetSymbolAddress((void**)&hbuf, g_h);
    cudaGetSymbolAddress((void**)&gw0,  g_gw0);
    cudaGetSymbolAddress((void**)&gw1,  g_gw1);
    cudaGetSymbolAddress((void**)&idx0, g_idx0);
    cudaGetSymbolAddress((void**)&idx1, g_idx1);
    cudaGetSymbolAddress((void**)&perm0, g_perm0);
    cudaGetSymbolAddress((void**)&perm1, g_perm1);
    cudaGetSymbolAddress((void**)&te0,  g_te0);
    cudaGetSymbolAddress((void**)&te1,  g_te1);

    int att_smem = ATT_SMEM_FLOATS * (int)sizeof(float);
    cudaFuncSetAttribute(attn_kernel, cudaFuncAttributeMaxDynamicSharedMemorySize, att_smem);

    // 1. attention gate + grouping
    gate_kernel<<<TKN, 256>>>(src, Wg_attn, idx0, gw0);
    scatter_kernel<<<1, 256>>>(idx0, perm0, te0);
    // 2. QKV projection (tf32 mma)
    moe_gemm_mma<<<dim3(3 * DM / 128, MAXTILES), 256>>>(
        src, Wqkv, bqkv, gw0, perm0, te0, qkv, DM, 3 * DM, 0);
    // 3. attention
    attn_kernel<<<dim3(1024 / 64, 2 * NH), 256, att_smem>>>(qkv, mask, ctx);
    // 4. output projection
    moe_gemm_mma<<<dim3(DM / 128, MAXTILES), 256>>>(
        ctx, Wo, bo, gw0, perm0, te0, tmp, DM, DM, 0);
    // 5. x = LN1(src + attn_out)
    ln_kernel<<<TKN, 256>>>(src, tmp, ln1_s, ln1_b, x);
    // 6. ffn gate + grouping
    gate_kernel<<<TKN, 256>>>(x, Wg_ffn, idx1, gw1);
    scatter_kernel<<<1, 256>>>(idx1, perm1, te1);
    // 7. h = gelu(gated W1)
    moe_gemm_mma<<<dim3(FFD / 128, MAXTILES), 256>>>(
        x, W1, b1, gw1, perm1, te1, hbuf, DM, FFD, 1);
    // 8. ffn = gated W2
    moe_gemm_mma<<<dim3(DM / 128, MAXTILES), 256>>>(
        hbuf, W2, b2, gw1, perm1, te1, tmp, FFD, DM, 0);
    // 9. out = LN2(x + ffn)
    ln_kernel<<<TKN, 256>>>(x, tmp, ln2_s, ln2_b, out);
}